// round 16
// baseline (speedup 1.0000x reference)
#include <cuda_runtime.h>
#include <math.h>

// features: (1, 50, 50, 1024) fp32 NHWC ; boxes: (1, 300, 4) fp32 [y1,x1,y2,x2]
// crop 14x14 bilinear, 2x2 max pool -> out (1, 300, 7, 7, 1024) fp32
// Block = (box, pooled-row py, channel-half). 128 threads, 1 float4 group each.
// Branchless 4-column pattern per px; rows hoisted per block (NR=2/3/4).
// Depth-2 px pipeline keeps ~16 loads/warp in flight (proven R10/R15 body).
// R16: streaming (evict-first) output stores keep write-once data from
// competing with feature reads in L2.

#define FH 50
#define FW 50
#define FC 1024
#define NBOX 300
#define CROP 14
#define PO 7
#define C4 (FC / 4)      // 256 float4 channel groups
#define TPB 128
#define ROWS4 (FW * C4)

__device__ __forceinline__ float4 wsum(const float4 tl, const float4 tr,
                                       const float4 bl, const float4 br,
                                       const float a, const float b)
{
    const float aa = 1.0f - a;
    const float bb = 1.0f - b;
    const float w0 = aa * bb, w1 = a * bb, w2 = aa * b, w3 = a * b;
    float4 v;
    v.x = fmaf(w3, br.x, fmaf(w2, bl.x, fmaf(w1, tr.x, w0 * tl.x)));
    v.y = fmaf(w3, br.y, fmaf(w2, bl.y, fmaf(w1, tr.y, w0 * tl.y)));
    v.z = fmaf(w3, br.z, fmaf(w2, bl.z, fmaf(w1, tr.z, w0 * tl.z)));
    v.w = fmaf(w3, br.w, fmaf(w2, bl.w, fmaf(w1, tr.w, w0 * tl.w)));
    return v;
}

__device__ __forceinline__ void max4(float4& m, const float4 v)
{
    m.x = fmaxf(m.x, v.x);
    m.y = fmaxf(m.y, v.y);
    m.z = fmaxf(m.z, v.z);
    m.w = fmaxf(m.w, v.w);
}

// Column offsets (float4 units) for sample pair at xs0 (incremental form).
__device__ __forceinline__ void px_cols(const float xs0, const float dx,
                                        int coff[4], float& wx0, float& wx1)
{
    const float xs1 = xs0 + dx;
    const float xf0 = floorf(xs0), xf1 = floorf(xs1);
    wx0 = xs0 - xf0;
    wx1 = xs1 - xf1;
    // Clamps never fire on in-range data; they only bound memory accesses.
    const int c0 = min(max((int)xf0, 0), FW - 2);
    const int c2 = min(max((int)xf1, 0), FW - 2);
    coff[0] = c0 * C4;
    coff[1] = coff[0] + C4;
    coff[2] = c2 * C4;
    coff[3] = coff[2] + C4;
}

// NR = distinct rows (2: same pair; 3: chain; 4: two pairs at distance dr).
// Top samples use rows (0,1); bottom samples use rows (NR-2, NR-1).
template <int NR>
__device__ __forceinline__ void do_row(
    const float4* __restrict__ prow,  // f4 + r0*ROWS4 + c4
    float4* __restrict__ orow,        // out + (box*49 + py*7)*C4 + c4
    const int dr,
    const float xbase, const float dx,
    const float wy0, const float wy1)
{
    int roff[NR];
    roff[0] = 0;
    roff[1] = ROWS4;
    if (NR == 3) { roff[2] = 2 * ROWS4; }
    if (NR == 4) { roff[2] = dr * ROWS4; roff[3] = roff[2] + ROWS4; }

    constexpr int RB = NR - 2;
    const float step = dx + dx;

    float4 g[2][NR][4];
    float wx0[2], wx1[2];

    // Prologue: issue px=0 loads.
    float xs_next = xbase;
    {
        int coff[4];
        px_cols(xs_next, dx, coff, wx0[0], wx1[0]);
#pragma unroll
        for (int i = 0; i < NR; i++)
#pragma unroll
            for (int j = 0; j < 4; j++)
                g[0][i][j] = prow[roff[i] + coff[j]];
    }

    float4* optr = orow;

#pragma unroll
    for (int px = 0; px < PO; px++) {
        const int cur = px & 1;
        const int nxt = cur ^ 1;

        // Issue px+1's loads BEFORE consuming px's data.
        if (px < PO - 1) {
            xs_next += step;
            int coff[4];
            px_cols(xs_next, dx, coff, wx0[nxt], wx1[nxt]);
#pragma unroll
            for (int i = 0; i < NR; i++)
#pragma unroll
                for (int j = 0; j < 4; j++)
                    g[nxt][i][j] = prow[roff[i] + coff[j]];
        }

        // Compute px from the current buffer.
        const float a0 = wx0[cur], a1 = wx1[cur];
        float4 m = wsum(g[cur][0][0], g[cur][0][1],
                        g[cur][1][0], g[cur][1][1], a0, wy0);
        max4(m, wsum(g[cur][0][2], g[cur][0][3],
                     g[cur][1][2], g[cur][1][3], a1, wy0));
        max4(m, wsum(g[cur][RB][0], g[cur][RB][1],
                     g[cur][RB + 1][0], g[cur][RB + 1][1], a0, wy1));
        max4(m, wsum(g[cur][RB][2], g[cur][RB][3],
                     g[cur][RB + 1][2], g[cur][RB + 1][3], a1, wy1));

        // Streaming store: write-once output, evict-first in L2.
        __stcs(optr, m);
        optr += C4;
    }
}

__global__ __launch_bounds__(TPB, 4)
void roi_pool_kernel(const float* __restrict__ feat,
                     const float* __restrict__ boxes,
                     float* __restrict__ out)
{
    const int bid  = blockIdx.x;           // 0 .. 4200
    const int n    = bid / (PO * 2);       // box
    const int rem  = bid - n * (PO * 2);
    const int py   = rem >> 1;             // pooled row
    const int c4   = (rem & 1) * TPB + threadIdx.x;

    const float4 box = __ldg(((const float4*)boxes) + n);

    const float scale = 1.0f / (float)(CROP - 1);
    const float dy = (box.z - box.x) * (float)(FH - 1) * scale;
    const float dx = (box.w - box.y) * (float)(FW - 1) * scale;
    const float xbase = box.y * (float)(FW - 1);

    const float ys0 = fmaf((float)(2 * py), dy, box.x * (float)(FH - 1));
    const float ys1 = ys0 + dy;
    const float yf0 = floorf(ys0), yf1 = floorf(ys1);
    const float wy0 = ys0 - yf0, wy1 = ys1 - yf1;

    // Clamps never fire on in-range data (coords in [0,49)).
    const int r0 = min(max((int)yf0, 0), FH - 2);
    const int r2 = min(max((int)yf1, 0), FH - 2);
    const int dr = r2 - r0;

    const float4* __restrict__ prow = (const float4*)feat + (r0 * ROWS4 + c4);
    float4* __restrict__ orow =
        (float4*)out + ((n * PO + py) * PO * C4 + c4);

    if (dr == 0)      do_row<2>(prow, orow, dr, xbase, dx, wy0, wy1);
    else if (dr == 1) do_row<3>(prow, orow, dr, xbase, dx, wy0, wy1);
    else              do_row<4>(prow, orow, dr, xbase, dx, wy0, wy1);
}

extern "C" void kernel_launch(void* const* d_in, const int* in_sizes, int n_in,
                              void* d_out, int out_size)
{
    const float* feat  = (const float*)d_in[0];
    const float* boxes = (const float*)d_in[1];
    float* out = (float*)d_out;

    roi_pool_kernel<<<NBOX * PO * 2, TPB>>>(feat, boxes, out);
}